// round 10
// baseline (speedup 1.0000x reference)
#include <cuda_runtime.h>
#include <cuda_fp16.h>
#include <mma.h>
#include <math.h>

using namespace nvcuda;

#define NN 100000
#define NE 1600000
#define NV 15000
#define DD 128
#define NG 16
#define NPAD 100352                 // 98 * 1024
#define NSCB 98                     // scan blocks (1024 counts each)
#define G0B  118                    // gemm0 blocks: 118*128 = 15104 >= NV

// ---------------- device scratch (static: no allocations allowed) ------------
__device__ int    g_off[NPAD + 4];
__device__ int    g_cursor[NPAD + 4];
__device__ int    g_bsum[NSCB];
__device__ int    g_tick0;                 // scan arrive counter
__device__ int    g_tick1;                 // gemm1 completion ticket
__device__ int2   g_meta[NE];              // {(wid<<17)|src, bits(w*norm[src])}
__device__ __half g_Ph[NV * DD];           // embeds @ W0 fp16 (L2-resident)
__device__ __half g_H0h[NN * DD];          // layer-1 output fp16
__device__ __half g_S1h[(NN + 64) * DD];   // N*A*N*H0 fp16 (padded for TC tiles)
__device__ __half g_W0h[DD * DD];
__device__ __half g_W1h[DD * DD];
__device__ float  g_pool[NG * DD];         // per-graph max (relu>=0 -> int cmp)

// ---------------- helpers ----------------------------------------------------
__device__ __forceinline__ void split_h2(float2 raw, float2& f0, float2& f1) {
    __half2 h0 = *reinterpret_cast<__half2*>(&raw.x);
    __half2 h1 = *reinterpret_cast<__half2*>(&raw.y);
    f0 = __half22float2(h0);
    f1 = __half22float2(h1);
}

// ---------------- 0: zero + W conversions + tickets --------------------------
__global__ void k_zero(const float* __restrict__ W0, const float* __restrict__ W1) {
    int i = blockIdx.x * 256 + threadIdx.x;
    if (i < NPAD + 4) g_off[i] = 0;
    if (i < NG * DD) g_pool[i] = 0.0f;
    if (i == 0) { g_tick0 = 0; g_tick1 = 0; }
    if (i < DD * DD) {
        g_W0h[i] = __float2half(W0[i]);
        g_W1h[i] = __float2half(W1[i]);
    }
}

// ---------------- 1: histogram -----------------------------------------------
__global__ void k_hist(const int* __restrict__ edst) {
    int e = blockIdx.x * 256 + threadIdx.x;
    if (e < NE) atomicAdd(&g_off[edst[e]], 1);
}

// ---------------- 2: single-kernel scan (resident spin barrier, 98 blocks) ---
__global__ __launch_bounds__(256) void k_scanF() {
    __shared__ int sm[256];
    __shared__ int red[128];
    __shared__ int s_base;
    int b = blockIdx.x, t = threadIdx.x;
    int4 c = ((const int4*)g_off)[b * 256 + t];
    int s = c.x + c.y + c.z + c.w;
    sm[t] = s;
    __syncthreads();
    for (int off = 1; off < 256; off <<= 1) {
        int u = (t >= off) ? sm[t - off] : 0;
        __syncthreads();
        sm[t] += u;
        __syncthreads();
    }
    int excl = sm[t] - s;
    int total = sm[255];

    // publish chunk total, arrive, spin until all 98 posted (all resident)
    if (t == 0) {
        g_bsum[b] = total;
        __threadfence();
        atomicAdd(&g_tick0, 1);
        while (atomicAdd(&g_tick0, 0) < NSCB) { }
    }
    __syncthreads();

    // block offset = sum of g_bsum[0..b-1]
    if (t < 128) red[t] = (t < b) ? __ldcg(&g_bsum[t]) : 0;
    __syncthreads();
    if (t < 64) red[t] += red[t + 64];
    __syncthreads();
    if (t < 32) {
        int v = red[t] + red[t + 32];
#pragma unroll
        for (int o = 16; o > 0; o >>= 1) v += __shfl_down_sync(0xffffffffu, v, o);
        if (t == 0) s_base = v;
    }
    __syncthreads();

    int base = s_base + excl;
    int4 o;
    o.x = base;
    o.y = base + c.x;
    o.z = o.y + c.y;
    o.w = o.z + c.z;
    ((int4*)g_off)[b * 256 + t] = o;
    ((int4*)g_cursor)[b * 256 + t] = o;
}

// ---------------- 3: merged scatter + gemm0 ----------------------------------
// blocks [0, G0B): gemm0 -- Ph = half(emb @ W0), 128 rows/block, 8 warps
// blocks [G0B, ..): scatter -- build meta in CSR order
__global__ __launch_bounds__(256) void k_scatter_gemm0(
        const int* __restrict__ esrc, const int* __restrict__ edst,
        const float* __restrict__ ew, const float* __restrict__ norm,
        const int* __restrict__ word_ids, const float* __restrict__ emb) {
    __shared__ __half Ah[128 * DD];   // 32 KB (gemm0 path; aliased as staging)
    if (blockIdx.x < G0B) {
        int rb = blockIdx.x * 128;
        for (int i = threadIdx.x; i < 128 * DD; i += 256) {
            int row = rb + (i >> 7);
            Ah[i] = (row < NV) ? __float2half(emb[row * DD + (i & 127)]) : __half(0.f);
        }
        __syncthreads();

        int warp = threadIdx.x >> 5;
        int lane = threadIdx.x & 31;
        wmma::fragment<wmma::accumulator, 16, 16, 16, float> acc[8];
#pragma unroll
        for (int n = 0; n < 8; n++) wmma::fill_fragment(acc[n], 0.0f);
#pragma unroll
        for (int k = 0; k < 8; k++) {
            wmma::fragment<wmma::matrix_a, 16, 16, 16, __half, wmma::row_major> af;
            wmma::load_matrix_sync(af, Ah + (warp * 16) * DD + k * 16, DD);
#pragma unroll
            for (int n = 0; n < 8; n++) {
                wmma::fragment<wmma::matrix_b, 16, 16, 16, __half, wmma::row_major> bf;
                wmma::load_matrix_sync(bf, g_W0h + (k * 16) * DD + n * 16, DD);
                wmma::mma_sync(acc[n], af, bf, acc[n]);
            }
        }
        __syncthreads();                       // all Ah reads done; alias as float staging
        float* St = (float*)Ah;                // per-warp 16x32 region: warp*512 floats
#pragma unroll
        for (int n = 0; n < 8; n += 2) {
            wmma::store_matrix_sync(St + warp * 512 +  0, acc[n],     32, wmma::mem_row_major);
            wmma::store_matrix_sync(St + warp * 512 + 16, acc[n + 1], 32, wmma::mem_row_major);
            __syncwarp();
#pragma unroll
            for (int r = 0; r < 16; r++) {
                int row = rb + warp * 16 + r;
                if (row < NV) {
                    float v = St[warp * 512 + r * 32 + lane];
                    g_Ph[row * DD + n * 16 + lane] = __float2half(v);
                }
            }
            __syncwarp();
        }
    } else {
        int e = (blockIdx.x - G0B) * 256 + threadIdx.x;
        if (e >= NE) return;
        int d = edst[e];
        int s = esrc[e];
        int pos = atomicAdd(&g_cursor[d], 1);
        float wn = ew[e] * __ldg(&norm[s]);
        int packed = s | (__ldg(&word_ids[s]) << 17);   // src < 2^17, wid < 2^14
        g_meta[pos] = make_int2(packed, __float_as_int(wn));
    }
}

// ---------------- 4/5: edge aggregation (warp per node, UNCHANGED) -----------
// MODE 0: acc = sum wn * Ph[wid];  H0h = half(relu(acc*norm[dst] + b0))
// MODE 1: acc = sum wn * H0h[src]; S1h = half(acc*norm[dst])
template <int MODE>
__global__ __launch_bounds__(256) void agg_k(const float* __restrict__ norm,
                                             const float* __restrict__ bias) {
    int node = (blockIdx.x * 256 + threadIdx.x) >> 5;
    if (node >= NN) return;
    int lane = threadIdx.x & 31;
    int beg = g_off[node], end = g_off[node + 1];
    const float2* tbl = (const float2*)((MODE == 0) ? g_Ph : g_H0h);

    float ax = 0.f, ay = 0.f, az = 0.f, aw = 0.f;
    int e = beg;
    for (; e + 8 <= end; e += 8) {
        int2 m[8];
#pragma unroll
        for (int j = 0; j < 8; j++) m[j] = __ldg(g_meta + e + j);
        float2 raw[8];
#pragma unroll
        for (int j = 0; j < 8; j++) {
            int idx = (MODE == 0) ? ((unsigned)m[j].x >> 17) : (m[j].x & 0x1FFFF);
            raw[j] = __ldg(tbl + idx * 32 + lane);
        }
#pragma unroll
        for (int j = 0; j < 8; j++) {
            float c = __int_as_float(m[j].y);
            float2 f0, f1; split_h2(raw[j], f0, f1);
            ax = fmaf(c, f0.x, ax); ay = fmaf(c, f0.y, ay);
            az = fmaf(c, f1.x, az); aw = fmaf(c, f1.y, aw);
        }
    }
    for (; e < end; e++) {
        int2 m = __ldg(g_meta + e);
        int idx = (MODE == 0) ? ((unsigned)m.x >> 17) : (m.x & 0x1FFFF);
        float2 raw = __ldg(tbl + idx * 32 + lane);
        float c = __int_as_float(m.y);
        float2 f0, f1; split_h2(raw, f0, f1);
        ax = fmaf(c, f0.x, ax); ay = fmaf(c, f0.y, ay);
        az = fmaf(c, f1.x, az); aw = fmaf(c, f1.y, aw);
    }
    float nd = __ldg(norm + node);
    float2 outp;
    if (MODE == 0) {
        float4 b = __ldg((const float4*)bias + lane);
        float rx = fmaxf(fmaf(ax, nd, b.x), 0.f);
        float ry = fmaxf(fmaf(ay, nd, b.y), 0.f);
        float rz = fmaxf(fmaf(az, nd, b.z), 0.f);
        float rw = fmaxf(fmaf(aw, nd, b.w), 0.f);
        *reinterpret_cast<__half2*>(&outp.x) = __floats2half2_rn(rx, ry);
        *reinterpret_cast<__half2*>(&outp.y) = __floats2half2_rn(rz, rw);
        ((float2*)g_H0h)[node * 32 + lane] = outp;
    } else {
        *reinterpret_cast<__half2*>(&outp.x) = __floats2half2_rn(ax * nd, ay * nd);
        *reinterpret_cast<__half2*>(&outp.y) = __floats2half2_rn(az * nd, aw * nd);
        ((float2*)g_S1h)[node * 32 + lane] = outp;
    }
}

// ---------------- 6: gemm1 + bias/relu/max-pool + fused head (last block) ----
__global__ __launch_bounds__(128) void gemm1_k(const float* __restrict__ bias,
                                               const int* __restrict__ gid,
                                               const float* __restrict__ Wout,
                                               const float* __restrict__ bout,
                                               const float* __restrict__ y,
                                               float* __restrict__ out,
                                               int out_size) {
    __shared__ float sm[64][DD];
    int warp = threadIdx.x >> 5;
    int lane = threadIdx.x & 31;
    int rb = blockIdx.x * 64;
    int row0 = rb + warp * 16;

    wmma::fragment<wmma::accumulator, 16, 16, 16, float> acc[8];
#pragma unroll
    for (int n = 0; n < 8; n++) wmma::fill_fragment(acc[n], 0.0f);

#pragma unroll
    for (int k = 0; k < 8; k++) {
        wmma::fragment<wmma::matrix_a, 16, 16, 16, __half, wmma::row_major> af;
        wmma::load_matrix_sync(af, g_S1h + row0 * DD + k * 16, DD);
#pragma unroll
        for (int n = 0; n < 8; n++) {
            wmma::fragment<wmma::matrix_b, 16, 16, 16, __half, wmma::row_major> bf;
            wmma::load_matrix_sync(bf, g_W1h + (k * 16) * DD + n * 16, DD);
            wmma::mma_sync(acc[n], af, bf, acc[n]);
        }
    }
#pragma unroll
    for (int n = 0; n < 8; n++)
        wmma::store_matrix_sync(&sm[warp * 16][n * 16], acc[n], DD, wmma::mem_row_major);
    __syncthreads();

    int col = threadIdx.x;
    float bv = __ldg(bias + col);
    int gfirst = __ldg(gid + rb);
    int lastrow = rb + 63; if (lastrow >= NN) lastrow = NN - 1;
    int glast = __ldg(gid + lastrow);
    if (gfirst == glast) {
        float m = 0.0f;
#pragma unroll 4
        for (int r = 0; r < 64; r++) {
            if (rb + r < NN)
                m = fmaxf(m, fmaxf(sm[r][col] + bv, 0.0f));
        }
        atomicMax((int*)&g_pool[gfirst * DD + col], __float_as_int(m));
    } else {
        for (int r = 0; r < 64; r++) {
            int row = rb + r;
            if (row < NN) {
                int gg = __ldg(gid + row);
                float v = fmaxf(sm[r][col] + bv, 0.0f);
                atomicMax((int*)&g_pool[gg * DD + col], __float_as_int(v));
            }
        }
    }

    // ---- fused head: last block to finish computes loss + sigmoid ----
    __threadfence();
    __shared__ bool isLast;
    if (threadIdx.x == 0)
        isLast = (atomicAdd(&g_tick1, 1) == (int)gridDim.x - 1);
    __syncthreads();
    if (!isLast) return;
    __threadfence();

    __shared__ float zbuf[NG];
#pragma unroll
    for (int gi = 0; gi < 4; gi++) {
        int g = warp * 4 + gi;
        float4 pv = __ldcg((const float4*)&g_pool[g * DD + lane * 4]);
        float4 wv = __ldg((const float4*)Wout + lane);
        float d = pv.x * wv.x + pv.y * wv.y + pv.z * wv.z + pv.w * wv.w;
#pragma unroll
        for (int o = 16; o > 0; o >>= 1) d += __shfl_xor_sync(0xffffffffu, d, o);
        if (lane == 0) zbuf[g] = d;
    }
    __syncthreads();
    if (threadIdx.x == 0) {
        float b0v = __ldg(bout);
        float L = 0.f;
        float preds[NG];
        for (int g = 0; g < NG; g++) {
            float z = zbuf[g] + b0v;
            float yd = __ldg(y + g);
            L += fmaxf(z, 0.f) - z * yd + log1pf(expf(-fabsf(z)));
            preds[g] = 1.f / (1.f + expf(-z));
        }
        L *= (1.f / NG);
        if (out_size >= NG + 1) {
            out[0] = L;
            for (int g = 0; g < NG; g++) out[1 + g] = preds[g];
            for (int i = NG + 1; i < out_size; i++) out[i] = 0.f;
        } else if (out_size == NG) {
            for (int g = 0; g < NG; g++) out[g] = preds[g];
        } else {
            out[0] = L;
        }
    }
}

// ---------------- launch -----------------------------------------------------
extern "C" void kernel_launch(void* const* d_in, const int* in_sizes, int n_in,
                              void* d_out, int out_size) {
    const int*   word_ids = (const int*)d_in[0];
    const int*   esrc     = (const int*)d_in[1];
    const int*   edst     = (const int*)d_in[2];
    const float* ew       = (const float*)d_in[3];
    const float* norm     = (const float*)d_in[4];
    const int*   gid      = (const int*)d_in[5];
    const float* y        = (const float*)d_in[6];
    const float* emb      = (const float*)d_in[7];
    const float* W0       = (const float*)d_in[8];
    const float* b0       = (const float*)d_in[9];
    const float* W1       = (const float*)d_in[10];
    const float* b1       = (const float*)d_in[11];
    const float* Wout     = (const float*)d_in[12];
    const float* bout     = (const float*)d_in[13];
    float* out = (float*)d_out;

    k_zero <<<(NPAD + 4 + 255) / 256, 256>>>(W0, W1);
    k_hist <<<(NE + 255) / 256, 256>>>(edst);
    k_scanF<<<NSCB, 256>>>();
    k_scatter_gemm0<<<G0B + (NE + 255) / 256, 256>>>(esrc, edst, ew, norm,
                                                     word_ids, emb);
    agg_k<0><<<(NN + 7) / 8, 256>>>(norm, b0);
    agg_k<1><<<(NN + 7) / 8, 256>>>(norm, nullptr);
    gemm1_k<<<(NN + 63) / 64, 128>>>(b1, gid, Wout, bout, y, out, out_size);
}

// round 11
// speedup vs baseline: 1.1238x; 1.1238x over previous
#include <cuda_runtime.h>
#include <cuda_fp16.h>
#include <mma.h>
#include <math.h>

using namespace nvcuda;

#define NN 100000
#define NE 1600000
#define NV 15000
#define DD 128
#define NG 16
#define NPAD 100352                 // 98 * 1024
#define NSCB 98                     // scan blocks (1024 counts each)

// ---------------- device scratch (static: no allocations allowed) ------------
__device__ int    g_off[NPAD + 4];
__device__ int    g_cursor[NPAD + 4];
__device__ int    g_bsum[NSCB];
__device__ int    g_tick0;                 // scan arrive counter
__device__ int    g_tick1;                 // gemm1 completion ticket
__device__ int2   g_meta[NE];              // {(wid<<17)|src, bits(w*norm[src])}
__device__ __half g_Ph[NV * DD];           // embeds @ W0 fp16 (L2-resident)
__device__ __half g_H0h[NN * DD];          // layer-1 output fp16
__device__ __half g_S1h[(NN + 64) * DD];   // N*A*N*H0 fp16 (padded for TC tiles)
__device__ __half g_W0h[DD * DD];
__device__ __half g_W1h[DD * DD];
__device__ float  g_pool[NG * DD];         // per-graph max (relu>=0 -> int cmp)

// ---------------- helpers ----------------------------------------------------
__device__ __forceinline__ void split_h2(float2 raw, float2& f0, float2& f1) {
    __half2 h0 = *reinterpret_cast<__half2*>(&raw.x);
    __half2 h1 = *reinterpret_cast<__half2*>(&raw.y);
    f0 = __half22float2(h0);
    f1 = __half22float2(h1);
}

// ---------------- 0: zero + W conversions + tickets --------------------------
__global__ void k_zero(const float* __restrict__ W0, const float* __restrict__ W1) {
    int i = blockIdx.x * 256 + threadIdx.x;
    if (i < NPAD + 4) g_off[i] = 0;
    if (i < NG * DD) g_pool[i] = 0.0f;
    if (i == 0) { g_tick0 = 0; g_tick1 = 0; }
    if (i < DD * DD) {
        g_W0h[i] = __float2half(W0[i]);
        g_W1h[i] = __float2half(W1[i]);
    }
}

// ---------------- 1: histogram -----------------------------------------------
__global__ void k_hist(const int* __restrict__ edst) {
    int e = blockIdx.x * 256 + threadIdx.x;
    if (e < NE) atomicAdd(&g_off[edst[e]], 1);
}

// ---------------- 2: single-kernel scan (resident spin barrier, 98 blocks) ---
__global__ __launch_bounds__(256) void k_scanF() {
    __shared__ int sm[256];
    __shared__ int red[128];
    __shared__ int s_base;
    int b = blockIdx.x, t = threadIdx.x;
    int4 c = ((const int4*)g_off)[b * 256 + t];
    int s = c.x + c.y + c.z + c.w;
    sm[t] = s;
    __syncthreads();
    for (int off = 1; off < 256; off <<= 1) {
        int u = (t >= off) ? sm[t - off] : 0;
        __syncthreads();
        sm[t] += u;
        __syncthreads();
    }
    int excl = sm[t] - s;
    int total = sm[255];

    // publish chunk total, arrive, spin until all 98 posted (all resident)
    if (t == 0) {
        g_bsum[b] = total;
        __threadfence();
        atomicAdd(&g_tick0, 1);
        while (atomicAdd(&g_tick0, 0) < NSCB) { }
    }
    __syncthreads();

    // block offset = sum of g_bsum[0..b-1]
    if (t < 128) red[t] = (t < b) ? __ldcg(&g_bsum[t]) : 0;
    __syncthreads();
    if (t < 64) red[t] += red[t + 64];
    __syncthreads();
    if (t < 32) {
        int v = red[t] + red[t + 32];
#pragma unroll
        for (int o = 16; o > 0; o >>= 1) v += __shfl_down_sync(0xffffffffu, v, o);
        if (t == 0) s_base = v;
    }
    __syncthreads();

    int base = s_base + excl;
    int4 o;
    o.x = base;
    o.y = base + c.x;
    o.z = o.y + c.y;
    o.w = o.z + c.z;
    ((int4*)g_off)[b * 256 + t] = o;
    ((int4*)g_cursor)[b * 256 + t] = o;
}

// ---------------- 3: scatter (standalone, low-footprint) ---------------------
__global__ void k_scatter(const int* __restrict__ esrc, const int* __restrict__ edst,
                          const float* __restrict__ ew, const float* __restrict__ norm,
                          const int* __restrict__ word_ids) {
    int e = blockIdx.x * 256 + threadIdx.x;
    if (e >= NE) return;
    int d = edst[e];
    int s = esrc[e];
    int pos = atomicAdd(&g_cursor[d], 1);
    float wn = ew[e] * __ldg(&norm[s]);
    int packed = s | (__ldg(&word_ids[s]) << 17);   // src < 2^17, wid < 2^14
    g_meta[pos] = make_int2(packed, __float_as_int(wn));
}

// ---------------- 4: gemm0 -- Ph = half(emb @ W0), inline fp32->fp16 ---------
__global__ __launch_bounds__(128) void gemm0_k(const float* __restrict__ emb) {
    __shared__ __half Ah[64 * DD];   // 16 KB
    __shared__ float St[64 * 32];    // 8 KB staging
    int rb = blockIdx.x * 64;
    for (int i = threadIdx.x; i < 64 * DD; i += 128) {
        int row = rb + (i >> 7);
        Ah[i] = (row < NV) ? __float2half(emb[row * DD + (i & 127)]) : __half(0.f);
    }
    __syncthreads();

    int warp = threadIdx.x >> 5;
    wmma::fragment<wmma::accumulator, 16, 16, 16, float> acc[8];
#pragma unroll
    for (int n = 0; n < 8; n++) wmma::fill_fragment(acc[n], 0.0f);
#pragma unroll
    for (int k = 0; k < 8; k++) {
        wmma::fragment<wmma::matrix_a, 16, 16, 16, __half, wmma::row_major> af;
        wmma::load_matrix_sync(af, Ah + (warp * 16) * DD + k * 16, DD);
#pragma unroll
        for (int n = 0; n < 8; n++) {
            wmma::fragment<wmma::matrix_b, 16, 16, 16, __half, wmma::row_major> bf;
            wmma::load_matrix_sync(bf, g_W0h + (k * 16) * DD + n * 16, DD);
            wmma::mma_sync(acc[n], af, bf, acc[n]);
        }
    }
    __syncthreads();
#pragma unroll
    for (int n = 0; n < 8; n += 2) {
        wmma::store_matrix_sync(&St[warp * 16 * 32 + 0],  acc[n],     32, wmma::mem_row_major);
        wmma::store_matrix_sync(&St[warp * 16 * 32 + 16], acc[n + 1], 32, wmma::mem_row_major);
        __syncwarp();
        int lane = threadIdx.x & 31;
#pragma unroll
        for (int r = 0; r < 16; r++) {
            int row = rb + warp * 16 + r;
            if (row < NV) {
                float v = St[warp * 16 * 32 + r * 32 + lane];
                g_Ph[row * DD + n * 16 + lane] = __float2half(v);
            }
        }
        __syncwarp();
    }
}

// ---------------- 5/6: edge aggregation (warp per node, UNCHANGED) -----------
// MODE 0: acc = sum wn * Ph[wid];  H0h = half(relu(acc*norm[dst] + b0))
// MODE 1: acc = sum wn * H0h[src]; S1h = half(acc*norm[dst])
template <int MODE>
__global__ __launch_bounds__(256) void agg_k(const float* __restrict__ norm,
                                             const float* __restrict__ bias) {
    int node = (blockIdx.x * 256 + threadIdx.x) >> 5;
    if (node >= NN) return;
    int lane = threadIdx.x & 31;
    int beg = g_off[node], end = g_off[node + 1];
    const float2* tbl = (const float2*)((MODE == 0) ? g_Ph : g_H0h);

    float ax = 0.f, ay = 0.f, az = 0.f, aw = 0.f;
    int e = beg;
    for (; e + 8 <= end; e += 8) {
        int2 m[8];
#pragma unroll
        for (int j = 0; j < 8; j++) m[j] = __ldg(g_meta + e + j);
        float2 raw[8];
#pragma unroll
        for (int j = 0; j < 8; j++) {
            int idx = (MODE == 0) ? ((unsigned)m[j].x >> 17) : (m[j].x & 0x1FFFF);
            raw[j] = __ldg(tbl + idx * 32 + lane);
        }
#pragma unroll
        for (int j = 0; j < 8; j++) {
            float c = __int_as_float(m[j].y);
            float2 f0, f1; split_h2(raw[j], f0, f1);
            ax = fmaf(c, f0.x, ax); ay = fmaf(c, f0.y, ay);
            az = fmaf(c, f1.x, az); aw = fmaf(c, f1.y, aw);
        }
    }
    for (; e < end; e++) {
        int2 m = __ldg(g_meta + e);
        int idx = (MODE == 0) ? ((unsigned)m.x >> 17) : (m.x & 0x1FFFF);
        float2 raw = __ldg(tbl + idx * 32 + lane);
        float c = __int_as_float(m.y);
        float2 f0, f1; split_h2(raw, f0, f1);
        ax = fmaf(c, f0.x, ax); ay = fmaf(c, f0.y, ay);
        az = fmaf(c, f1.x, az); aw = fmaf(c, f1.y, aw);
    }
    float nd = __ldg(norm + node);
    float2 outp;
    if (MODE == 0) {
        float4 b = __ldg((const float4*)bias + lane);
        float rx = fmaxf(fmaf(ax, nd, b.x), 0.f);
        float ry = fmaxf(fmaf(ay, nd, b.y), 0.f);
        float rz = fmaxf(fmaf(az, nd, b.z), 0.f);
        float rw = fmaxf(fmaf(aw, nd, b.w), 0.f);
        *reinterpret_cast<__half2*>(&outp.x) = __floats2half2_rn(rx, ry);
        *reinterpret_cast<__half2*>(&outp.y) = __floats2half2_rn(rz, rw);
        ((float2*)g_H0h)[node * 32 + lane] = outp;
    } else {
        *reinterpret_cast<__half2*>(&outp.x) = __floats2half2_rn(ax * nd, ay * nd);
        *reinterpret_cast<__half2*>(&outp.y) = __floats2half2_rn(az * nd, aw * nd);
        ((float2*)g_S1h)[node * 32 + lane] = outp;
    }
}

// ---------------- 7: gemm1 + bias/relu/max-pool + fused head (last block) ----
__global__ __launch_bounds__(128) void gemm1_k(const float* __restrict__ bias,
                                               const int* __restrict__ gid,
                                               const float* __restrict__ Wout,
                                               const float* __restrict__ bout,
                                               const float* __restrict__ y,
                                               float* __restrict__ out,
                                               int out_size) {
    __shared__ float sm[64][DD];
    int warp = threadIdx.x >> 5;
    int lane = threadIdx.x & 31;
    int rb = blockIdx.x * 64;
    int row0 = rb + warp * 16;

    wmma::fragment<wmma::accumulator, 16, 16, 16, float> acc[8];
#pragma unroll
    for (int n = 0; n < 8; n++) wmma::fill_fragment(acc[n], 0.0f);

#pragma unroll
    for (int k = 0; k < 8; k++) {
        wmma::fragment<wmma::matrix_a, 16, 16, 16, __half, wmma::row_major> af;
        wmma::load_matrix_sync(af, g_S1h + row0 * DD + k * 16, DD);
#pragma unroll
        for (int n = 0; n < 8; n++) {
            wmma::fragment<wmma::matrix_b, 16, 16, 16, __half, wmma::row_major> bf;
            wmma::load_matrix_sync(bf, g_W1h + (k * 16) * DD + n * 16, DD);
            wmma::mma_sync(acc[n], af, bf, acc[n]);
        }
    }
#pragma unroll
    for (int n = 0; n < 8; n++)
        wmma::store_matrix_sync(&sm[warp * 16][n * 16], acc[n], DD, wmma::mem_row_major);
    __syncthreads();

    int col = threadIdx.x;
    float bv = __ldg(bias + col);
    int gfirst = __ldg(gid + rb);
    int lastrow = rb + 63; if (lastrow >= NN) lastrow = NN - 1;
    int glast = __ldg(gid + lastrow);
    if (gfirst == glast) {
        float m = 0.0f;
#pragma unroll 4
        for (int r = 0; r < 64; r++) {
            if (rb + r < NN)
                m = fmaxf(m, fmaxf(sm[r][col] + bv, 0.0f));
        }
        atomicMax((int*)&g_pool[gfirst * DD + col], __float_as_int(m));
    } else {
        for (int r = 0; r < 64; r++) {
            int row = rb + r;
            if (row < NN) {
                int gg = __ldg(gid + row);
                float v = fmaxf(sm[r][col] + bv, 0.0f);
                atomicMax((int*)&g_pool[gg * DD + col], __float_as_int(v));
            }
        }
    }

    // ---- fused head: last block to finish computes loss + sigmoid ----
    __threadfence();
    __shared__ bool isLast;
    if (threadIdx.x == 0)
        isLast = (atomicAdd(&g_tick1, 1) == (int)gridDim.x - 1);
    __syncthreads();
    if (!isLast) return;
    __threadfence();

    __shared__ float zbuf[NG];
#pragma unroll
    for (int gi = 0; gi < 4; gi++) {
        int g = warp * 4 + gi;
        float4 pv = __ldcg((const float4*)&g_pool[g * DD + lane * 4]);
        float4 wv = __ldg((const float4*)Wout + lane);
        float d = pv.x * wv.x + pv.y * wv.y + pv.z * wv.z + pv.w * wv.w;
#pragma unroll
        for (int o = 16; o > 0; o >>= 1) d += __shfl_xor_sync(0xffffffffu, d, o);
        if (lane == 0) zbuf[g] = d;
    }
    __syncthreads();
    if (threadIdx.x == 0) {
        float b0v = __ldg(bout);
        float L = 0.f;
        float preds[NG];
        for (int g = 0; g < NG; g++) {
            float z = zbuf[g] + b0v;
            float yd = __ldg(y + g);
            L += fmaxf(z, 0.f) - z * yd + log1pf(expf(-fabsf(z)));
            preds[g] = 1.f / (1.f + expf(-z));
        }
        L *= (1.f / NG);
        if (out_size >= NG + 1) {
            out[0] = L;
            for (int g = 0; g < NG; g++) out[1 + g] = preds[g];
            for (int i = NG + 1; i < out_size; i++) out[i] = 0.f;
        } else if (out_size == NG) {
            for (int g = 0; g < NG; g++) out[g] = preds[g];
        } else {
            out[0] = L;
        }
    }
}

// ---------------- launch -----------------------------------------------------
extern "C" void kernel_launch(void* const* d_in, const int* in_sizes, int n_in,
                              void* d_out, int out_size) {
    const int*   word_ids = (const int*)d_in[0];
    const int*   esrc     = (const int*)d_in[1];
    const int*   edst     = (const int*)d_in[2];
    const float* ew       = (const float*)d_in[3];
    const float* norm     = (const float*)d_in[4];
    const int*   gid      = (const int*)d_in[5];
    const float* y        = (const float*)d_in[6];
    const float* emb      = (const float*)d_in[7];
    const float* W0       = (const float*)d_in[8];
    const float* b0       = (const float*)d_in[9];
    const float* W1       = (const float*)d_in[10];
    const float* b1       = (const float*)d_in[11];
    const float* Wout     = (const float*)d_in[12];
    const float* bout     = (const float*)d_in[13];
    float* out = (float*)d_out;

    k_zero   <<<(NPAD + 4 + 255) / 256, 256>>>(W0, W1);
    k_hist   <<<(NE + 255) / 256, 256>>>(edst);
    k_scanF  <<<NSCB, 256>>>();
    k_scatter<<<(NE + 255) / 256, 256>>>(esrc, edst, ew, norm, word_ids);
    gemm0_k  <<<(NV + 63) / 64, 128>>>(emb);

    agg_k<0> <<<(NN + 7) / 8, 256>>>(norm, b0);
    agg_k<1> <<<(NN + 7) / 8, 256>>>(norm, nullptr);
    gemm1_k  <<<(NN + 63) / 64, 128>>>(b1, gid, Wout, bout, y, out, out_size);
}